// round 3
// baseline (speedup 1.0000x reference)
#include <cuda_runtime.h>

// ---------------- scratch ----------------
__device__ float g_Gpart[8 * 64 * 64 * 64];   // split-K gram partials (8 MB)
__device__ float g_m1part[8 * 64 * 64];       // token-sum partials
__device__ float g_M2[8 * 64 * 64 * 2];       // mixing matrix, DUPLICATED pairs {m,m}
__device__ float g_cst[1];

typedef unsigned long long ull;

__device__ __forceinline__ void ffma2(ull& d, ull a, ull b) {
    asm("fma.rn.f32x2 %0, %1, %2, %0;" : "+l"(d) : "l"(a), "l"(b));
}
__device__ __forceinline__ float2 unpack2(ull v) {
    float2 r; asm("mov.b64 {%0, %1}, %2;" : "=f"(r.x), "=f"(r.y) : "l"(v)); return r;
}

// ---------------- K1: Gram partials ----------------
// grid (8 batches, 64 y-rows), 256 threads. One image row per block (k=64).
// T2[token][64 k + pad4]; stride 68 floats -> conflict-free LDS.128.
__global__ __launch_bounds__(256) void gram_kernel(const float* __restrict__ x) {
    int b = blockIdx.x, y = blockIdx.y;
    __shared__ __align__(16) float T2[64 * 68];
    const float* xb = x + b * 262144;
    int tid = threadIdx.x;

    #pragma unroll
    for (int it = 0; it < 4; ++it) {
        int i4 = tid + it * 256;            // 0..1023
        int j = i4 >> 4, x4 = i4 & 15;
        float4 v = *(const float4*)(xb + ((j >> 3) * 64 + y) * 512 + (j & 7) * 64 + (x4 << 2));
        *(float4*)&T2[j * 68 + (x4 << 2)] = v;
    }
    __syncthreads();

    int w = tid >> 5, l = tid & 31, rb = w << 3;   // 8 gram rows per warp
    ull acc[16];
    #pragma unroll
    for (int i = 0; i < 16; ++i) acc[i] = 0ull;

    #pragma unroll 4
    for (int k = 0; k < 64; k += 4) {
        ulonglong2 bv0 = *(const ulonglong2*)&T2[l * 68 + k];          // lane-varying .128
        ulonglong2 bv1 = *(const ulonglong2*)&T2[(l + 32) * 68 + k];
        #pragma unroll
        for (int u = 0; u < 8; ++u) {
            ulonglong2 a = *(const ulonglong2*)&T2[(rb + u) * 68 + k]; // broadcast .128
            ffma2(acc[2 * u],     a.x, bv0.x);
            ffma2(acc[2 * u],     a.y, bv0.y);
            ffma2(acc[2 * u + 1], a.x, bv1.x);
            ffma2(acc[2 * u + 1], a.y, bv1.y);
        }
    }

    if (tid < 64) {
        float s = 0.f;
        #pragma unroll 8
        for (int k = 0; k < 64; ++k) s += T2[tid * 68 + k];
        g_m1part[(b * 64 + y) * 64 + tid] = s;
    }

    float* gp = &g_Gpart[(b * 64 + y) * 4096];
    #pragma unroll
    for (int u = 0; u < 8; ++u) {
        float2 p0 = unpack2(acc[2 * u]);
        float2 p1 = unpack2(acc[2 * u + 1]);
        gp[(rb + u) * 64 + l]      = p0.x + p0.y;
        gp[(rb + u) * 64 + l + 32] = p1.x + p1.y;
    }
}

// ---------------- K2: consts + reduce + softmax + mixing matrix ----------------
// grid (8 batches, 8 row-groups of 8), 256 threads.
__global__ __launch_bounds__(256) void attn_kernel(
        const float* __restrict__ w1, const float* __restrict__ b1,
        const float* __restrict__ wqkv, const float* __restrict__ wproj,
        const float* __restrict__ bproj, const float* __restrict__ w2,
        const float* __restrict__ b2) {
    int b = blockIdx.x, i0 = blockIdx.y * 8, tid = threadIdx.x;
    __shared__ float A[96], B0[96], tC[32];
    __shared__ float sal[4], sbe[4], sga[4], sde[4], swh[4];
    __shared__ float Gs[512], Ms[512], m1s[64];

    // ---- weight collapse (tiny, redundant per block) ----
    if (tid < 96) {
        float a = 0.f, bb = 0.f;
        #pragma unroll
        for (int c = 0; c < 32; ++c) {
            float wv = wqkv[tid * 32 + c];
            a += wv * w1[c];
            bb += wv * b1[c];
        }
        A[tid] = a; B0[tid] = bb;
    }
    if (tid >= 128 && tid < 160) {
        int c = tid - 128;
        float s = 0.f;
        #pragma unroll
        for (int o = 0; o < 32; ++o) s += w2[o] * wproj[o * 32 + c];
        tC[c] = s;
    }
    __syncthreads();
    if (tid < 4) {
        float al = 0.f, be = 0.f, ga = 0.f, de = 0.f, wh = 0.f;
        #pragma unroll
        for (int dd = 0; dd < 8; ++dd) {
            int c = tid * 8 + dd;
            float aq = A[c], ak = A[32 + c], bq = B0[c], bk = B0[32 + c];
            al += aq * ak; be += aq * bk; ga += bq * ak; de += bq * bk;
            wh += tC[c] * A[64 + c];
        }
        sal[tid] = al; sbe[tid] = be; sga[tid] = ga; sde[tid] = de; swh[tid] = wh;
    }
    if (tid == 4) {
        float c = b2[0];
        #pragma unroll
        for (int o = 0; o < 32; ++o) c += w2[o] * bproj[o];
        #pragma unroll
        for (int cc = 0; cc < 32; ++cc) c += tC[cc] * B0[64 + cc];
        g_cst[0] = c;   // identical from every block (deterministic)
    }

    // ---- reduce this block's 8 Gram rows + m1 over 64 chunks ----
    const float* gp = &g_Gpart[b * 64 * 4096 + i0 * 64];
    #pragma unroll
    for (int rep = 0; rep < 2; ++rep) {
        int e = tid + rep * 256;
        float s = 0.f;
        #pragma unroll 8
        for (int c = 0; c < 64; ++c) s += gp[c * 4096 + e];
        Gs[e] = s;
    }
    if (tid < 64) {
        const float* mp = &g_m1part[b * 64 * 64];
        float s = 0.f;
        #pragma unroll 8
        for (int c = 0; c < 64; ++c) s += mp[c * 64 + tid];
        m1s[tid] = s;
    }
    __syncthreads();

    // ---- softmax: warp w owns row i0+w ----
    int w = tid >> 5, l = tid & 31;
    const float scale = 1.0f / (4096.0f * 2.8284271247461903f);
    float g0 = Gs[w * 64 + l], g1 = Gs[w * 64 + l + 32];
    float m1i = m1s[i0 + w], m1l = m1s[l], m1l2 = m1s[l + 32];
    float acc0 = 0.f, acc1 = 0.f;
    #pragma unroll
    for (int h = 0; h < 4; ++h) {
        float al = sal[h] * scale, be = sbe[h] * scale;
        float ga = sga[h] * scale, de = sde[h] * scale * 4096.f;
        float whh = swh[h];
        float base = be * m1i + de;
        float s0 = al * g0 + ga * m1l  + base;
        float s1 = al * g1 + ga * m1l2 + base;
        float mx = fmaxf(s0, s1);
        #pragma unroll
        for (int off = 16; off > 0; off >>= 1)
            mx = fmaxf(mx, __shfl_xor_sync(0xffffffffu, mx, off));
        float e0 = __expf(s0 - mx), e1 = __expf(s1 - mx);
        float sm = e0 + e1;
        #pragma unroll
        for (int off = 16; off > 0; off >>= 1)
            sm += __shfl_xor_sync(0xffffffffu, sm, off);
        float f = whh / sm;
        acc0 += e0 * f; acc1 += e1 * f;
    }
    Ms[w * 64 + l] = acc0;
    Ms[w * 64 + l + 32] = acc1;
    __syncthreads();

    // ---- write DUPLICATED mixing matrix {m, m} ----
    float* mo = &g_M2[b * 8192 + i0 * 128];
    #pragma unroll
    for (int rep = 0; rep < 2; ++rep) {
        int idx = tid + rep * 256;
        float v = Ms[idx];
        ((float2*)mo)[idx] = make_float2(v, v);
    }
}

// ---------------- K3: out = M @ X + const ----------------
// grid (8 batches, 64 y-rows), 256 threads. V in natural [j][x] layout
// (x-pair packed per lane); M pre-duplicated -> broadcast LDS.128.
__global__ __launch_bounds__(256) void out_kernel(const float* __restrict__ x,
                                                  float* __restrict__ out) {
    int b = blockIdx.x, y = blockIdx.y;
    int tid = threadIdx.x;
    __shared__ __align__(16) float M2[64 * 64 * 2];  // [s][j] duplicated pairs
    __shared__ __align__(16) float V[64 * 68];       // [j][x]

    const float* mg = &g_M2[b * 8192];
    #pragma unroll
    for (int it = 0; it < 8; ++it)
        ((float4*)M2)[tid + it * 256] = ((const float4*)mg)[tid + it * 256];

    const float* xb = x + b * 262144;
    #pragma unroll
    for (int it = 0; it < 4; ++it) {
        int i4 = tid + it * 256;
        int j = i4 >> 4, x4 = i4 & 15;
        float4 v = *(const float4*)(xb + ((j >> 3) * 64 + y) * 512 + (j & 7) * 64 + (x4 << 2));
        *(float4*)&V[j * 68 + (x4 << 2)] = v;
    }
    __syncthreads();

    int w = tid >> 5, l = tid & 31, rb = w << 3;
    ull acc[8];
    #pragma unroll
    for (int i = 0; i < 8; ++i) acc[i] = 0ull;

    #pragma unroll 8
    for (int j = 0; j < 64; j += 2) {
        ull v0 = *(const ull*)&V[j * 68 + 2 * l];         // x-pair, lane-varying
        ull v1 = *(const ull*)&V[(j + 1) * 68 + 2 * l];
        #pragma unroll
        for (int u = 0; u < 8; ++u) {
            ulonglong2 m = *(const ulonglong2*)&M2[((rb + u) * 64 + j) * 2]; // {mj,mj},{mj1,mj1}
            ffma2(acc[u], m.x, v0);
            ffma2(acc[u], m.y, v1);
        }
    }

    float cst = g_cst[0];
    float* ob = out + b * 262144;
    #pragma unroll
    for (int u = 0; u < 8; ++u) {
        int s = rb + u;
        float2 p = unpack2(acc[u]);
        int base = ((s >> 3) * 64 + y) * 512 + (s & 7) * 64;
        *(float2*)&ob[base + 2 * l] = make_float2(p.x + cst, p.y + cst);
    }
}

extern "C" void kernel_launch(void* const* d_in, const int* in_sizes, int n_in,
                              void* d_out, int out_size) {
    const float* x     = (const float*)d_in[0];
    const float* w1    = (const float*)d_in[3];
    const float* b1    = (const float*)d_in[4];
    const float* wqkv  = (const float*)d_in[5];
    const float* wproj = (const float*)d_in[6];
    const float* bproj = (const float*)d_in[7];
    const float* w2    = (const float*)d_in[8];
    const float* b2    = (const float*)d_in[9];
    float* out = (float*)d_out;

    gram_kernel<<<dim3(8, 64), 256>>>(x);
    attn_kernel<<<dim3(8, 8), 256>>>(w1, b1, wqkv, wproj, bproj, w2, b2);
    out_kernel<<<dim3(8, 64), 256>>>(x, out);
}

// round 4
// speedup vs baseline: 1.1803x; 1.1803x over previous
#include <cuda_runtime.h>

// ---------------- scratch ----------------
__device__ float g_Gpart[8 * 64 * 64 * 64];   // split-K gram partials (8 MB)
__device__ float g_m1part[8 * 64 * 64];       // token-sum partials
__device__ float g_Mt[8 * 64 * 64];           // mixing matrix TRANSPOSED [b][j][s]
__device__ float g_cst[1];

typedef unsigned long long ull;

__device__ __forceinline__ void ffma2(ull& d, ull a, ull b) {
    asm("fma.rn.f32x2 %0, %1, %2, %0;" : "+l"(d) : "l"(a), "l"(b));
}
__device__ __forceinline__ ull pack2(float x, float y) {
    ull r; asm("mov.b64 %0, {%1, %2};" : "=l"(r) : "f"(x), "f"(y)); return r;
}
__device__ __forceinline__ float2 unpack2(ull v) {
    float2 r; asm("mov.b64 {%0, %1}, %2;" : "=f"(r.x), "=f"(r.y) : "l"(v)); return r;
}
__device__ __forceinline__ ull add2(ull a, ull b) {
    ull r; asm("add.rn.f32x2 %0, %1, %2;" : "=l"(r) : "l"(a), "l"(b)); return r;
}

// padded row: 68 words; 8-word col-block for tile t starts at off8(t)
__device__ __forceinline__ int off8(int t) { return 8 * t + (t >= 4 ? 4 : 0); }

// shared inner product: acc[u][v] over 8x8 tile, k-loop of 64, operands in
// padded smem rows (stride 68). Ta: broadcast rows, Tb: lane-varying cols.
__device__ __forceinline__ void mm8x8(const float* Ta, const float* Tb, ull acc[8][4]) {
    #pragma unroll 2
    for (int p = 0; p < 64; ++p) {
        const float* ra = Ta + p * 68;
        const float* rb = Tb + p * 68;
        float4 bA = *(const float4*)rb;
        float4 bB = *(const float4*)(rb + 4);
        float4 aA = *(const float4*)ra;
        float4 aB = *(const float4*)(ra + 4);
        ull b0 = pack2(bA.x, bA.y), b1 = pack2(bA.z, bA.w);
        ull b2 = pack2(bB.x, bB.y), b3 = pack2(bB.z, bB.w);
        float av[8] = {aA.x, aA.y, aA.z, aA.w, aB.x, aB.y, aB.z, aB.w};
        #pragma unroll
        for (int u = 0; u < 8; ++u) {
            ull ad = pack2(av[u], av[u]);
            ffma2(acc[u][0], ad, b0);
            ffma2(acc[u][1], ad, b1);
            ffma2(acc[u][2], ad, b2);
            ffma2(acc[u][3], ad, b3);
        }
    }
}

// ---------------- K1: Gram partials ----------------
// grid 512 (b*64+y), 64 threads. T[p][token-padded], k = 64 x-positions.
__global__ __launch_bounds__(64, 8) void gram_kernel(const float* __restrict__ x) {
    int b = blockIdx.x >> 6, y = blockIdx.x & 63;
    __shared__ __align__(16) float T[64 * 68];
    const float* xb = x + b * 262144 + y * 512;
    int tid = threadIdx.x;

    // fill with 4x4 register transpose: tile (jg: 4 tokens, c: 4 points)
    #pragma unroll
    for (int t = 0; t < 4; ++t) {
        int tile = tid + 64 * t;
        int c = tile & 15, jg = tile >> 4;           // c: p-group, jg: token-group
        const float* src = xb + (jg >> 1) * 32768 + (jg & 1) * 256 + 4 * c;
        float4 q0 = *(const float4*)(src);
        float4 q1 = *(const float4*)(src + 64);
        float4 q2 = *(const float4*)(src + 128);
        float4 q3 = *(const float4*)(src + 192);
        int pw = (4 * c) * 68 + 4 * jg + (jg >= 8 ? 4 : 0);
        *(float4*)&T[pw]       = make_float4(q0.x, q1.x, q2.x, q3.x);
        *(float4*)&T[pw + 68]  = make_float4(q0.y, q1.y, q2.y, q3.y);
        *(float4*)&T[pw + 136] = make_float4(q0.z, q1.z, q2.z, q3.z);
        *(float4*)&T[pw + 204] = make_float4(q0.w, q1.w, q2.w, q3.w);
    }
    __syncthreads();

    int ti = tid >> 3, tj = tid & 7;
    ull acc[8][4];
    #pragma unroll
    for (int u = 0; u < 8; ++u)
        #pragma unroll
        for (int v = 0; v < 4; ++v) acc[u][v] = 0ull;

    mm8x8(T + off8(ti), T + off8(tj), acc);

    // m1 partial: thread tid sums token tid (conflict-free column reads)
    {
        float s = 0.f;
        int o = tid + (tid >= 32 ? 4 : 0);
        #pragma unroll 8
        for (int p = 0; p < 64; ++p) s += T[p * 68 + o];
        g_m1part[(b * 64 + y) * 64 + tid] = s;
    }

    float* gp = &g_Gpart[(b * 64 + y) * 4096 + ti * 512 + tj * 8];
    #pragma unroll
    for (int u = 0; u < 8; ++u) {
        *(ulonglong2*)(gp + u * 64)     = make_ulonglong2(acc[u][0], acc[u][1]);
        *(ulonglong2*)(gp + u * 64 + 4) = make_ulonglong2(acc[u][2], acc[u][3]);
    }
}

// ---------------- K2: consts + reduce + softmax + transposed M ----------------
// grid (8 batches, 16 row-groups of 4), 256 threads.
__global__ __launch_bounds__(256) void attn_kernel(
        const float* __restrict__ w1, const float* __restrict__ b1,
        const float* __restrict__ wqkv, const float* __restrict__ wproj,
        const float* __restrict__ bproj, const float* __restrict__ w2,
        const float* __restrict__ b2) {
    int b = blockIdx.x, i0 = blockIdx.y * 4, tid = threadIdx.x;
    __shared__ float A[96], B0[96], tC[32];
    __shared__ float sal[4], sbe[4], sga[4], sde[4], swh[4];
    __shared__ float Gs[256], m1s[64];

    // weight collapse (tiny, redundant per block)
    if (tid < 96) {
        float a = 0.f, bb = 0.f;
        #pragma unroll
        for (int c = 0; c < 32; ++c) {
            float wv = wqkv[tid * 32 + c];
            a += wv * w1[c];
            bb += wv * b1[c];
        }
        A[tid] = a; B0[tid] = bb;
    }
    if (tid >= 128 && tid < 160) {
        int c = tid - 128;
        float s = 0.f;
        #pragma unroll
        for (int o = 0; o < 32; ++o) s += w2[o] * wproj[o * 32 + c];
        tC[c] = s;
    }
    __syncthreads();
    if (tid < 4) {
        float al = 0.f, be = 0.f, ga = 0.f, de = 0.f, wh = 0.f;
        #pragma unroll
        for (int dd = 0; dd < 8; ++dd) {
            int c = tid * 8 + dd;
            float aq = A[c], ak = A[32 + c], bq = B0[c], bk = B0[32 + c];
            al += aq * ak; be += aq * bk; ga += bq * ak; de += bq * bk;
            wh += tC[c] * A[64 + c];
        }
        sal[tid] = al; sbe[tid] = be; sga[tid] = ga; sde[tid] = de; swh[tid] = wh;
    }
    if (tid == 4) {
        float c = b2[0];
        #pragma unroll
        for (int o = 0; o < 32; ++o) c += w2[o] * bproj[o];
        #pragma unroll
        for (int cc = 0; cc < 32; ++cc) c += tC[cc] * B0[64 + cc];
        g_cst[0] = c;   // identical value from every block
    }

    // reduce 4 Gram rows (64-deep split-K) + m1
    {
        const float* gp = &g_Gpart[b * 64 * 4096 + i0 * 64];
        float s = 0.f;
        #pragma unroll 8
        for (int c = 0; c < 64; ++c) s += gp[c * 4096 + tid];
        Gs[tid] = s;
    }
    if (tid < 64) {
        const float* mp = &g_m1part[b * 64 * 64];
        float s = 0.f;
        #pragma unroll 8
        for (int c = 0; c < 64; ++c) s += mp[c * 64 + tid];
        m1s[tid] = s;
    }
    __syncthreads();

    // softmax: warps 0-3, warp w owns row i0+w (2 cols per lane)
    int w = tid >> 5, l = tid & 31;
    if (w < 4) {
        const float scale = 1.0f / (4096.0f * 2.8284271247461903f);
        float g0 = Gs[w * 64 + l], g1 = Gs[w * 64 + l + 32];
        float m1i = m1s[i0 + w], m1l = m1s[l], m1l2 = m1s[l + 32];
        float acc0 = 0.f, acc1 = 0.f;
        #pragma unroll
        for (int h = 0; h < 4; ++h) {
            float al = sal[h] * scale, be = sbe[h] * scale;
            float ga = sga[h] * scale, de = sde[h] * scale * 4096.f;
            float whh = swh[h];
            float base = be * m1i + de;
            float s0 = al * g0 + ga * m1l  + base;
            float s1 = al * g1 + ga * m1l2 + base;
            float mx = fmaxf(s0, s1);
            #pragma unroll
            for (int off = 16; off > 0; off >>= 1)
                mx = fmaxf(mx, __shfl_xor_sync(0xffffffffu, mx, off));
            float e0 = __expf(s0 - mx), e1 = __expf(s1 - mx);
            float sm = e0 + e1;
            #pragma unroll
            for (int off = 16; off > 0; off >>= 1)
                sm += __shfl_xor_sync(0xffffffffu, sm, off);
            float f = whh / sm;
            acc0 += e0 * f; acc1 += e1 * f;
        }
        // transposed store: g_Mt[b][j][i]
        int i = i0 + w;
        g_Mt[b * 4096 + l * 64 + i] = acc0;
        g_Mt[b * 4096 + (l + 32) * 64 + i] = acc1;
    }
}

// ---------------- K3: out = M @ X + const ----------------
// grid 512 (b*64+y), 64 threads. Mt[j][s-padded], V[j][x-padded].
__global__ __launch_bounds__(64, 8) void out_kernel(const float* __restrict__ x,
                                                    float* __restrict__ out) {
    int b = blockIdx.x >> 6, y = blockIdx.x & 63;
    __shared__ __align__(16) float Mt[64 * 68];
    __shared__ __align__(16) float V[64 * 68];
    int tid = threadIdx.x;

    const float* mg = &g_Mt[b * 4096];
    const float* xb = x + b * 262144 + y * 512;
    #pragma unroll
    for (int t = 0; t < 16; ++t) {
        int i4 = tid + 64 * t;               // 0..1023
        int j = i4 >> 4, c = i4 & 15;
        int pw = j * 68 + 4 * c + (c >= 8 ? 4 : 0);
        *(float4*)&Mt[pw] = *(const float4*)(mg + j * 64 + 4 * c);
        *(float4*)&V[pw]  = *(const float4*)(xb + (j >> 3) * 32768 + (j & 7) * 64 + 4 * c);
    }
    __syncthreads();

    int ti = tid >> 3, tj = tid & 7;
    ull acc[8][4];
    #pragma unroll
    for (int u = 0; u < 8; ++u)
        #pragma unroll
        for (int v = 0; v < 4; ++v) acc[u][v] = 0ull;

    mm8x8(Mt + off8(ti), V + off8(tj), acc);

    float cst = g_cst[0];
    ull c2 = pack2(cst, cst);
    float* ob = out + b * 262144 + y * 512;
    #pragma unroll
    for (int u = 0; u < 8; ++u) {
        int s = ti * 8 + u;
        float* dst = ob + (s >> 3) * 32768 + (s & 7) * 64 + tj * 8;
        *(ulonglong2*)dst       = make_ulonglong2(add2(acc[u][0], c2), add2(acc[u][1], c2));
        *(ulonglong2*)(dst + 4) = make_ulonglong2(add2(acc[u][2], c2), add2(acc[u][3], c2));
    }
}

extern "C" void kernel_launch(void* const* d_in, const int* in_sizes, int n_in,
                              void* d_out, int out_size) {
    const float* x     = (const float*)d_in[0];
    const float* w1    = (const float*)d_in[3];
    const float* b1    = (const float*)d_in[4];
    const float* wqkv  = (const float*)d_in[5];
    const float* wproj = (const float*)d_in[6];
    const float* bproj = (const float*)d_in[7];
    const float* w2    = (const float*)d_in[8];
    const float* b2    = (const float*)d_in[9];
    float* out = (float*)d_out;

    gram_kernel<<<512, 64>>>(x);
    attn_kernel<<<dim3(8, 16), 256>>>(w1, b1, wqkv, wproj, bproj, w2, b2);
    out_kernel<<<512, 64>>>(x, out);
}